// round 14
// baseline (speedup 1.0000x reference)
#include <cuda_runtime.h>
#include <cuda_fp16.h>

#define POOLED 7
#define KSIZE  2
#define CROP   (POOLED * KSIZE)   // 14
#define HH     50
#define WW     50
#define CC     512
#define CPIX   128                // 8-byte (4 x fp16) groups per pixel
#define NROI   256

typedef unsigned long long u64;

// 5.12 MB fp16 feature-map scratch (NHWC), stored as u64 for LDG.64
__device__ u64 g_fmh[2 * HH * WW * CPIX];

// bit-cast halves of a u64 into __half2 (register renames, no instructions)
__device__ __forceinline__ __half2 h2lo(u64 v) {
    unsigned x = (unsigned)v;
    return *reinterpret_cast<__half2*>(&x);
}
__device__ __forceinline__ __half2 h2hi(u64 v) {
    unsigned x = (unsigned)(v >> 32);
    return *reinterpret_cast<__half2*>(&x);
}

// ---- pre-pass: fp32 -> fp16, 32B in / 16B out per thread ----
__global__ void __launch_bounds__(256)
conv_kernel(const float4* __restrict__ in) {
    const int i = blockIdx.x * 256 + threadIdx.x;    // 320,000 exact
    float4 v0 = in[2 * i];
    float4 v1 = in[2 * i + 1];
    ulonglong2 q;
    {
        __half2 a = __floats2half2_rn(v0.x, v0.y);
        __half2 b = __floats2half2_rn(v0.z, v0.w);
        unsigned ua = *reinterpret_cast<unsigned*>(&a);
        unsigned ub = *reinterpret_cast<unsigned*>(&b);
        q.x = (u64)ua | ((u64)ub << 32);
    }
    {
        __half2 a = __floats2half2_rn(v1.x, v1.y);
        __half2 b = __floats2half2_rn(v1.z, v1.w);
        unsigned ua = *reinterpret_cast<unsigned*>(&a);
        unsigned ub = *reinterpret_cast<unsigned*>(&b);
        q.y = (u64)ua | ((u64)ub << 32);
    }
    ((ulonglong2*)g_fmh)[i] = q;
}

__global__ void __launch_bounds__(128, 10)
roi_pool_kernel(const float* __restrict__ rois,
                float* __restrict__ out) {
    const int blk = blockIdx.x;             // 0 .. 256*7-1 = n*7 + ph
    const int n  = blk / POOLED;
    const int ph = blk - n * POOLED;
    const int b  = n >> 7;

    // rois flat: n*4 + {0:x1, 1:y1, 2:x2, 3:y2} — external input, safe pre-sync
    const float4 rr = __ldg((const float4*)rois + n);
    const float sy = (rr.w - rr.y) * (float)(HH - 1) / (float)(CROP - 1);
    const float sx = (rr.z - rr.x) * (float)(WW - 1) / (float)(CROP - 1);
    const float by = rr.y * (float)(HH - 1);
    const float bx = rr.x * (float)(WW - 1);

    // rois in [0,1) -> all samples in-range (masks identically 1; clamps kept)
    int y0i[KSIZE], y1i[KSIZE];
    __half2 wyh[KSIZE], uyh[KSIZE];
#pragma unroll
    for (int ky = 0; ky < KSIZE; ky++) {
        const float i  = (float)(KSIZE * ph + ky);
        const float ys = by + i * sy;
        const float y0f = floorf(ys);
        const float w   = ys - y0f;
        wyh[ky] = __float2half2_rn(w);
        uyh[ky] = __float2half2_rn(1.0f - w);
        int y0 = min(max((int)y0f, 0), HH - 1);
        y0i[ky] = y0;
        y1i[ky] = min(y0 + 1, HH - 1);
    }

    const int c4 = threadIdx.x;
    const u64* __restrict__ base = g_fmh + b * (HH * WW * CPIX) + c4;
    const u64* __restrict__ R0 = base + y0i[0] * (WW * CPIX);
    const u64* __restrict__ R1 = base + y1i[0] * (WW * CPIX);
    const u64* __restrict__ R2 = base + y0i[1] * (WW * CPIX);
    const u64* __restrict__ R3 = base + y1i[1] * (WW * CPIX);

    float4* __restrict__ outp = (float4*)out + (blk * POOLED) * CPIX + c4;

#if __CUDA_ARCH__ >= 900
    // PDL: all setup above ran while conv_kernel was still executing.
    // Block here until conv_kernel's g_fmh writes are visible.
    cudaGridDependencySynchronize();
#endif

#pragma unroll 1
    for (int pw = 0; pw < POOLED; pw++) {
        // ---- per-pw x setup ----
        int o0, o1, o2, o3;
        __half2 wxh[KSIZE], uxh[KSIZE];
        {
            const float j  = (float)(KSIZE * pw);
            const float xs = bx + j * sx;
            const float x0f = floorf(xs);
            const float w   = xs - x0f;
            wxh[0] = __float2half2_rn(w);
            uxh[0] = __float2half2_rn(1.0f - w);
            int x0 = min(max((int)x0f, 0), WW - 1);
            o0 = x0 * CPIX;
            o1 = min(x0 + 1, WW - 1) * CPIX;
        }
        {
            const float j  = (float)(KSIZE * pw + 1);
            const float xs = bx + j * sx;
            const float x0f = floorf(xs);
            const float w   = xs - x0f;
            wxh[1] = __float2half2_rn(w);
            uxh[1] = __float2half2_rn(1.0f - w);
            int x0 = min(max((int)x0f, 0), WW - 1);
            o2 = x0 * CPIX;
            o3 = min(x0 + 1, WW - 1) * CPIX;
        }

        // ---- 16 independent LDG.64, all up front (MLP=16, 32 regs) ----
        u64 h00 = R0[o0], h01 = R0[o1], h02 = R0[o2], h03 = R0[o3];
        u64 h10 = R1[o0], h11 = R1[o1], h12 = R1[o2], h13 = R1[o3];
        u64 h20 = R2[o0], h21 = R2[o1], h22 = R2[o2], h23 = R2[o3];
        u64 h30 = R3[o0], h31 = R3[o1], h32 = R3[o2], h33 = R3[o3];

        __half2 bl = __float2half2_rn(-65504.0f);
        __half2 bh = __float2half2_rn(-65504.0f);

        {   // ky0 kx0: rows h00 (y0) / h10 (y1), cols o0/o1
            __half2 t0l = __hfma2(h2lo(h00), uyh[0], __hmul2(h2lo(h10), wyh[0]));
            __half2 t0h = __hfma2(h2hi(h00), uyh[0], __hmul2(h2hi(h10), wyh[0]));
            __half2 t1l = __hfma2(h2lo(h01), uyh[0], __hmul2(h2lo(h11), wyh[0]));
            __half2 t1h = __hfma2(h2hi(h01), uyh[0], __hmul2(h2hi(h11), wyh[0]));
            __half2 vl  = __hfma2(t0l, uxh[0], __hmul2(t1l, wxh[0]));
            __half2 vh  = __hfma2(t0h, uxh[0], __hmul2(t1h, wxh[0]));
            bl = __hmax2(bl, vl);
            bh = __hmax2(bh, vh);
        }
        {   // ky0 kx1: cols o2/o3
            __half2 t0l = __hfma2(h2lo(h02), uyh[0], __hmul2(h2lo(h12), wyh[0]));
            __half2 t0h = __hfma2(h2hi(h02), uyh[0], __hmul2(h2hi(h12), wyh[0]));
            __half2 t1l = __hfma2(h2lo(h03), uyh[0], __hmul2(h2lo(h13), wyh[0]));
            __half2 t1h = __hfma2(h2hi(h03), uyh[0], __hmul2(h2hi(h13), wyh[0]));
            __half2 vl  = __hfma2(t0l, uxh[1], __hmul2(t1l, wxh[1]));
            __half2 vh  = __hfma2(t0h, uxh[1], __hmul2(t1h, wxh[1]));
            bl = __hmax2(bl, vl);
            bh = __hmax2(bh, vh);
        }
        {   // ky1 kx0: rows h20 (y0) / h30 (y1)
            __half2 t0l = __hfma2(h2lo(h20), uyh[1], __hmul2(h2lo(h30), wyh[1]));
            __half2 t0h = __hfma2(h2hi(h20), uyh[1], __hmul2(h2hi(h30), wyh[1]));
            __half2 t1l = __hfma2(h2lo(h21), uyh[1], __hmul2(h2lo(h31), wyh[1]));
            __half2 t1h = __hfma2(h2hi(h21), uyh[1], __hmul2(h2hi(h31), wyh[1]));
            __half2 vl  = __hfma2(t0l, uxh[0], __hmul2(t1l, wxh[0]));
            __half2 vh  = __hfma2(t0h, uxh[0], __hmul2(t1h, wxh[0]));
            bl = __hmax2(bl, vl);
            bh = __hmax2(bh, vh);
        }
        {   // ky1 kx1
            __half2 t0l = __hfma2(h2lo(h22), uyh[1], __hmul2(h2lo(h32), wyh[1]));
            __half2 t0h = __hfma2(h2hi(h22), uyh[1], __hmul2(h2hi(h32), wyh[1]));
            __half2 t1l = __hfma2(h2lo(h23), uyh[1], __hmul2(h2lo(h33), wyh[1]));
            __half2 t1h = __hfma2(h2hi(h23), uyh[1], __hmul2(h2hi(h33), wyh[1]));
            __half2 vl  = __hfma2(t0l, uxh[1], __hmul2(t1l, wxh[1]));
            __half2 vh  = __hfma2(t0h, uxh[1], __hmul2(t1h, wxh[1]));
            bl = __hmax2(bl, vl);
            bh = __hmax2(bh, vh);
        }

        float4 res;
        res.x = __low2float(bl);
        res.y = __high2float(bl);
        res.z = __low2float(bh);
        res.w = __high2float(bh);
        outp[pw * CPIX] = res;
    }
}

extern "C" void kernel_launch(void* const* d_in, const int* in_sizes, int n_in,
                              void* d_out, int out_size) {
    const float* fm   = (const float*)d_in[0];   // (2,50,50,512) f32
    const float* rois = (const float*)d_in[1];   // (2,128,4) f32
    float* out = (float*)d_out;                  // (256,7,7,512) f32

    conv_kernel<<<1250, 256>>>((const float4*)fm);       // 320,000 threads exact

    // PDL launch: roi kernel spins up + runs setup while conv executes;
    // blocks at cudaGridDependencySynchronize() until conv's writes land.
    cudaLaunchConfig_t cfg = {};
    cfg.gridDim = dim3(NROI * POOLED, 1, 1);             // 1792 blocks
    cfg.blockDim = dim3(128, 1, 1);
    cfg.dynamicSmemBytes = 0;
    cfg.stream = 0;
    cudaLaunchAttribute attr[1];
    attr[0].id = cudaLaunchAttributeProgrammaticStreamSerialization;
    attr[0].val.programmaticStreamSerializationAllowed = 1;
    cfg.attrs = attr;
    cfg.numAttrs = 1;
    cudaError_t e = cudaLaunchKernelEx(&cfg, roi_pool_kernel,
                                       (const float*)rois, (float*)out);
    if (e != cudaSuccess) {
        // Fallback: plain serialized launch (identical semantics)
        roi_pool_kernel<<<NROI * POOLED, 128>>>(rois, out);
    }
}

// round 15
// speedup vs baseline: 1.0934x; 1.0934x over previous
#include <cuda_runtime.h>
#include <cuda_fp16.h>

#define POOLED 7
#define KSIZE  2
#define CROP   (POOLED * KSIZE)   // 14
#define HH     50
#define WW     50
#define CC     512
#define CPIX   128                // 8-byte (4 x fp16) groups per pixel
#define NROI   256
#define NCELL  (NROI * POOLED * POOLED)   // 12544
#define NBLK   1184               // 148 SMs x 8 — provably co-resident (<=51 regs, 10/SM cap)

typedef unsigned long long u64;

// 5.12 MB fp16 feature-map scratch (NHWC), stored as u64 for LDG.64
__device__ u64 g_fmh[2 * HH * WW * CPIX];
// grid-barrier counter (accumulates across replays; phase = ctr / NBLK)
__device__ unsigned g_ctr = 0;

// bit-cast halves of a u64 into __half2 (register renames, no instructions)
__device__ __forceinline__ __half2 h2lo(u64 v) {
    unsigned x = (unsigned)v;
    return *reinterpret_cast<__half2*>(&x);
}
__device__ __forceinline__ __half2 h2hi(u64 v) {
    unsigned x = (unsigned)(v >> 32);
    return *reinterpret_cast<__half2*>(&x);
}

__global__ void __launch_bounds__(128, 10)
fused_kernel(const float4* __restrict__ fm,
             const float* __restrict__ rois,
             float* __restrict__ out) {
    const int tid = threadIdx.x;
    const int blk = blockIdx.x;

    // ================= Phase 1: fp32 -> fp16 conversion =================
    // 640,000 u64 outputs, grid-stride (4-5 items/thread)
    for (int i = blk * 128 + tid; i < 2 * HH * WW * CPIX; i += NBLK * 128) {
        float4 v = fm[i];
        __half2 a = __floats2half2_rn(v.x, v.y);
        __half2 b = __floats2half2_rn(v.z, v.w);
        unsigned ua = *reinterpret_cast<unsigned*>(&a);
        unsigned ub = *reinterpret_cast<unsigned*>(&b);
        g_fmh[i] = (u64)ua | ((u64)ub << 32);
    }

    // ================= Grid barrier (all NBLK blocks co-resident) =======
    __threadfence();           // release g_fmh writes
    __syncthreads();           // whole block done converting
    if (tid == 0) {
        unsigned old = atomicAdd(&g_ctr, 1u);
        unsigned target = (old / NBLK + 1u) * NBLK;
        unsigned cur;
        do {
            asm volatile("ld.acquire.gpu.u32 %0, [%1];"
                         : "=r"(cur) : "l"(&g_ctr));
            if (cur >= target) break;
            __nanosleep(32);
        } while (true);
    }
    __syncthreads();           // broadcast barrier-done to the block

    // ================= Phase 2: ROI pool, persistent per-cell loop ======
    const int c4 = threadIdx.x;
    for (int cell = blk; cell < NCELL; cell += NBLK) {
        const int n  = cell / (POOLED * POOLED);
        const int pp = cell - n * (POOLED * POOLED);
        const int ph = pp / POOLED;
        const int pw = pp - ph * POOLED;
        const int b  = n >> 7;

        // rois flat: n*4 + {0:x1, 1:y1, 2:x2, 3:y2}
        const float4 rr = __ldg((const float4*)rois + n);
        const float sy = (rr.w - rr.y) * (float)(HH - 1) / (float)(CROP - 1);
        const float sx = (rr.z - rr.x) * (float)(WW - 1) / (float)(CROP - 1);
        const float by = rr.y * (float)(HH - 1);
        const float bx = rr.x * (float)(WW - 1);

        // rois in [0,1) -> all samples in-range (clamps kept)
        int y0i[KSIZE], y1i[KSIZE];
        __half2 wyh[KSIZE], uyh[KSIZE];
#pragma unroll
        for (int ky = 0; ky < KSIZE; ky++) {
            const float i  = (float)(KSIZE * ph + ky);
            const float ys = by + i * sy;
            const float y0f = floorf(ys);
            const float w   = ys - y0f;
            wyh[ky] = __float2half2_rn(w);
            uyh[ky] = __float2half2_rn(1.0f - w);
            int y0 = min(max((int)y0f, 0), HH - 1);
            y0i[ky] = y0;
            y1i[ky] = min(y0 + 1, HH - 1);
        }

        int o0, o1, o2, o3;
        __half2 wxh[KSIZE], uxh[KSIZE];
#pragma unroll
        for (int kx = 0; kx < KSIZE; kx++) {
            const float j  = (float)(KSIZE * pw + kx);
            const float xs = bx + j * sx;
            const float x0f = floorf(xs);
            const float w   = xs - x0f;
            wxh[kx] = __float2half2_rn(w);
            uxh[kx] = __float2half2_rn(1.0f - w);
            int x0 = min(max((int)x0f, 0), WW - 1);
            int x1 = min(x0 + 1, WW - 1);
            if (kx == 0) { o0 = x0 * CPIX; o1 = x1 * CPIX; }
            else         { o2 = x0 * CPIX; o3 = x1 * CPIX; }
        }

        const u64* __restrict__ base = g_fmh + b * (HH * WW * CPIX) + c4;
        const u64* __restrict__ R0 = base + y0i[0] * (WW * CPIX);
        const u64* __restrict__ R1 = base + y1i[0] * (WW * CPIX);
        const u64* __restrict__ R2 = base + y0i[1] * (WW * CPIX);
        const u64* __restrict__ R3 = base + y1i[1] * (WW * CPIX);

        // ---- 16 independent LDG.64, all up front (MLP=16) ----
        u64 h00 = R0[o0], h01 = R0[o1], h02 = R0[o2], h03 = R0[o3];
        u64 h10 = R1[o0], h11 = R1[o1], h12 = R1[o2], h13 = R1[o3];
        u64 h20 = R2[o0], h21 = R2[o1], h22 = R2[o2], h23 = R2[o3];
        u64 h30 = R3[o0], h31 = R3[o1], h32 = R3[o2], h33 = R3[o3];

        __half2 bl = __float2half2_rn(-65504.0f);
        __half2 bh = __float2half2_rn(-65504.0f);

        {   // ky0 kx0
            __half2 t0l = __hfma2(h2lo(h00), uyh[0], __hmul2(h2lo(h10), wyh[0]));
            __half2 t0h = __hfma2(h2hi(h00), uyh[0], __hmul2(h2hi(h10), wyh[0]));
            __half2 t1l = __hfma2(h2lo(h01), uyh[0], __hmul2(h2lo(h11), wyh[0]));
            __half2 t1h = __hfma2(h2hi(h01), uyh[0], __hmul2(h2hi(h11), wyh[0]));
            __half2 vl  = __hfma2(t0l, uxh[0], __hmul2(t1l, wxh[0]));
            __half2 vh  = __hfma2(t0h, uxh[0], __hmul2(t1h, wxh[0]));
            bl = __hmax2(bl, vl);
            bh = __hmax2(bh, vh);
        }
        {   // ky0 kx1
            __half2 t0l = __hfma2(h2lo(h02), uyh[0], __hmul2(h2lo(h12), wyh[0]));
            __half2 t0h = __hfma2(h2hi(h02), uyh[0], __hmul2(h2hi(h12), wyh[0]));
            __half2 t1l = __hfma2(h2lo(h03), uyh[0], __hmul2(h2lo(h13), wyh[0]));
            __half2 t1h = __hfma2(h2hi(h03), uyh[0], __hmul2(h2hi(h13), wyh[0]));
            __half2 vl  = __hfma2(t0l, uxh[1], __hmul2(t1l, wxh[1]));
            __half2 vh  = __hfma2(t0h, uxh[1], __hmul2(t1h, wxh[1]));
            bl = __hmax2(bl, vl);
            bh = __hmax2(bh, vh);
        }
        {   // ky1 kx0
            __half2 t0l = __hfma2(h2lo(h20), uyh[1], __hmul2(h2lo(h30), wyh[1]));
            __half2 t0h = __hfma2(h2hi(h20), uyh[1], __hmul2(h2hi(h30), wyh[1]));
            __half2 t1l = __hfma2(h2lo(h21), uyh[1], __hmul2(h2lo(h31), wyh[1]));
            __half2 t1h = __hfma2(h2hi(h21), uyh[1], __hmul2(h2hi(h31), wyh[1]));
            __half2 vl  = __hfma2(t0l, uxh[0], __hmul2(t1l, wxh[0]));
            __half2 vh  = __hfma2(t0h, uxh[0], __hmul2(t1h, wxh[0]));
            bl = __hmax2(bl, vl);
            bh = __hmax2(bh, vh);
        }
        {   // ky1 kx1
            __half2 t0l = __hfma2(h2lo(h22), uyh[1], __hmul2(h2lo(h32), wyh[1]));
            __half2 t0h = __hfma2(h2hi(h22), uyh[1], __hmul2(h2hi(h32), wyh[1]));
            __half2 t1l = __hfma2(h2lo(h23), uyh[1], __hmul2(h2lo(h33), wyh[1]));
            __half2 t1h = __hfma2(h2hi(h23), uyh[1], __hmul2(h2hi(h33), wyh[1]));
            __half2 vl  = __hfma2(t0l, uxh[1], __hmul2(t1l, wxh[1]));
            __half2 vh  = __hfma2(t0h, uxh[1], __hmul2(t1h, wxh[1]));
            bl = __hmax2(bl, vl);
            bh = __hmax2(bh, vh);
        }

        float4 res;
        res.x = __low2float(bl);
        res.y = __high2float(bl);
        res.z = __low2float(bh);
        res.w = __high2float(bh);
        ((float4*)out)[cell * CPIX + c4] = res;
    }
}

extern "C" void kernel_launch(void* const* d_in, const int* in_sizes, int n_in,
                              void* d_out, int out_size) {
    const float* fm   = (const float*)d_in[0];   // (2,50,50,512) f32
    const float* rois = (const float*)d_in[1];   // (2,128,4) f32
    float* out = (float*)d_out;                  // (256,7,7,512) f32

    fused_kernel<<<NBLK, 128>>>((const float4*)fm, rois, out);
}

// round 16
// speedup vs baseline: 1.3750x; 1.2575x over previous
#include <cuda_runtime.h>
#include <cuda_fp16.h>

#define POOLED 7
#define KSIZE  2
#define CROP   (POOLED * KSIZE)   // 14
#define HH     50
#define WW     50
#define CC     512
#define CPIX   128                // 8-byte (4 x fp16) groups per pixel
#define NROI   256

typedef unsigned long long u64;

// 5.12 MB fp16 feature-map scratch (NHWC), stored as u64 for LDG.64
__device__ u64 g_fmh[2 * HH * WW * CPIX];

// bit-cast halves of a u64 into __half2 (register renames, no instructions)
__device__ __forceinline__ __half2 h2lo(u64 v) {
    unsigned x = (unsigned)v;
    return *reinterpret_cast<__half2*>(&x);
}
__device__ __forceinline__ __half2 h2hi(u64 v) {
    unsigned x = (unsigned)(v >> 32);
    return *reinterpret_cast<__half2*>(&x);
}

// ---- pre-pass: fp32 -> fp16, 32B in / 16B out per thread ----
__global__ void __launch_bounds__(256)
conv_kernel(const float4* __restrict__ in) {
    const int i = blockIdx.x * 256 + threadIdx.x;    // 320,000 exact
    float4 v0 = in[2 * i];
    float4 v1 = in[2 * i + 1];
    ulonglong2 q;
    {
        __half2 a = __floats2half2_rn(v0.x, v0.y);
        __half2 b = __floats2half2_rn(v0.z, v0.w);
        unsigned ua = *reinterpret_cast<unsigned*>(&a);
        unsigned ub = *reinterpret_cast<unsigned*>(&b);
        q.x = (u64)ua | ((u64)ub << 32);
    }
    {
        __half2 a = __floats2half2_rn(v1.x, v1.y);
        __half2 b = __floats2half2_rn(v1.z, v1.w);
        unsigned ua = *reinterpret_cast<unsigned*>(&a);
        unsigned ub = *reinterpret_cast<unsigned*>(&b);
        q.y = (u64)ua | ((u64)ub << 32);
    }
    ((ulonglong2*)g_fmh)[i] = q;
}

struct XW {
    int o0, o1, o2, o3;
    __half2 wx0, ux0, wx1, ux1;
};

__device__ __forceinline__ XW xsetup(float bx, float sx, int pw) {
    XW r;
    {
        const float j  = (float)(KSIZE * pw);
        const float xs = bx + j * sx;
        const float x0f = floorf(xs);
        const float w   = xs - x0f;
        r.wx0 = __float2half2_rn(w);
        r.ux0 = __float2half2_rn(1.0f - w);
        int x0 = min(max((int)x0f, 0), WW - 1);
        r.o0 = x0 * CPIX;
        r.o1 = min(x0 + 1, WW - 1) * CPIX;
    }
    {
        const float j  = (float)(KSIZE * pw + 1);
        const float xs = bx + j * sx;
        const float x0f = floorf(xs);
        const float w   = xs - x0f;
        r.wx1 = __float2half2_rn(w);
        r.ux1 = __float2half2_rn(1.0f - w);
        int x0 = min(max((int)x0f, 0), WW - 1);
        r.o2 = x0 * CPIX;
        r.o3 = min(x0 + 1, WW - 1) * CPIX;
    }
    return r;
}

#define LOAD16(H, X)                                                      \
    do {                                                                  \
        H[0]  = R0[(X).o0]; H[1]  = R0[(X).o1];                           \
        H[2]  = R0[(X).o2]; H[3]  = R0[(X).o3];                           \
        H[4]  = R1[(X).o0]; H[5]  = R1[(X).o1];                           \
        H[6]  = R1[(X).o2]; H[7]  = R1[(X).o3];                           \
        H[8]  = R2[(X).o0]; H[9]  = R2[(X).o1];                           \
        H[10] = R2[(X).o2]; H[11] = R2[(X).o3];                           \
        H[12] = R3[(X).o0]; H[13] = R3[(X).o1];                           \
        H[14] = R3[(X).o2]; H[15] = R3[(X).o3];                           \
    } while (0)

__device__ __forceinline__ void compute_cell(
    const u64* H, const XW& X,
    __half2 wy0, __half2 uy0, __half2 wy1, __half2 uy1,
    float4* outp)
{
    __half2 bl = __float2half2_rn(-65504.0f);
    __half2 bh = __float2half2_rn(-65504.0f);

    {   // ky0 kx0: rows H0 (y0) / H4 (y1), cols o0/o1
        __half2 t0l = __hfma2(h2lo(H[0]), uy0, __hmul2(h2lo(H[4]), wy0));
        __half2 t0h = __hfma2(h2hi(H[0]), uy0, __hmul2(h2hi(H[4]), wy0));
        __half2 t1l = __hfma2(h2lo(H[1]), uy0, __hmul2(h2lo(H[5]), wy0));
        __half2 t1h = __hfma2(h2hi(H[1]), uy0, __hmul2(h2hi(H[5]), wy0));
        __half2 vl  = __hfma2(t0l, X.ux0, __hmul2(t1l, X.wx0));
        __half2 vh  = __hfma2(t0h, X.ux0, __hmul2(t1h, X.wx0));
        bl = __hmax2(bl, vl);
        bh = __hmax2(bh, vh);
    }
    {   // ky0 kx1: cols o2/o3
        __half2 t0l = __hfma2(h2lo(H[2]), uy0, __hmul2(h2lo(H[6]), wy0));
        __half2 t0h = __hfma2(h2hi(H[2]), uy0, __hmul2(h2hi(H[6]), wy0));
        __half2 t1l = __hfma2(h2lo(H[3]), uy0, __hmul2(h2lo(H[7]), wy0));
        __half2 t1h = __hfma2(h2hi(H[3]), uy0, __hmul2(h2hi(H[7]), wy0));
        __half2 vl  = __hfma2(t0l, X.ux1, __hmul2(t1l, X.wx1));
        __half2 vh  = __hfma2(t0h, X.ux1, __hmul2(t1h, X.wx1));
        bl = __hmax2(bl, vl);
        bh = __hmax2(bh, vh);
    }
    {   // ky1 kx0: rows H8 (y0) / H12 (y1)
        __half2 t0l = __hfma2(h2lo(H[8]),  uy1, __hmul2(h2lo(H[12]), wy1));
        __half2 t0h = __hfma2(h2hi(H[8]),  uy1, __hmul2(h2hi(H[12]), wy1));
        __half2 t1l = __hfma2(h2lo(H[9]),  uy1, __hmul2(h2lo(H[13]), wy1));
        __half2 t1h = __hfma2(h2hi(H[9]),  uy1, __hmul2(h2hi(H[13]), wy1));
        __half2 vl  = __hfma2(t0l, X.ux0, __hmul2(t1l, X.wx0));
        __half2 vh  = __hfma2(t0h, X.ux0, __hmul2(t1h, X.wx0));
        bl = __hmax2(bl, vl);
        bh = __hmax2(bh, vh);
    }
    {   // ky1 kx1
        __half2 t0l = __hfma2(h2lo(H[10]), uy1, __hmul2(h2lo(H[14]), wy1));
        __half2 t0h = __hfma2(h2hi(H[10]), uy1, __hmul2(h2hi(H[14]), wy1));
        __half2 t1l = __hfma2(h2lo(H[11]), uy1, __hmul2(h2lo(H[15]), wy1));
        __half2 t1h = __hfma2(h2hi(H[11]), uy1, __hmul2(h2hi(H[15]), wy1));
        __half2 vl  = __hfma2(t0l, X.ux1, __hmul2(t1l, X.wx1));
        __half2 vh  = __hfma2(t0h, X.ux1, __hmul2(t1h, X.wx1));
        bl = __hmax2(bl, vl);
        bh = __hmax2(bh, vh);
    }

    float4 res;
    res.x = __low2float(bl);
    res.y = __high2float(bl);
    res.z = __low2float(bh);
    res.w = __high2float(bh);
    *outp = res;
}

__global__ void __launch_bounds__(128)
roi_pool_kernel(const float* __restrict__ rois,
                float* __restrict__ out) {
    const int blk = blockIdx.x;             // 0 .. 256*7-1 = n*7 + ph
    const int n  = blk / POOLED;
    const int ph = blk - n * POOLED;
    const int b  = n >> 7;

    // rois flat: n*4 + {0:x1, 1:y1, 2:x2, 3:y2}
    const float4 rr = __ldg((const float4*)rois + n);
    const float sy = (rr.w - rr.y) * (float)(HH - 1) / (float)(CROP - 1);
    const float sx = (rr.z - rr.x) * (float)(WW - 1) / (float)(CROP - 1);
    const float by = rr.y * (float)(HH - 1);
    const float bx = rr.x * (float)(WW - 1);

    // rois in [0,1) -> all samples in-range (clamps kept)
    int y0i[KSIZE], y1i[KSIZE];
    __half2 wyh[KSIZE], uyh[KSIZE];
#pragma unroll
    for (int ky = 0; ky < KSIZE; ky++) {
        const float i  = (float)(KSIZE * ph + ky);
        const float ys = by + i * sy;
        const float y0f = floorf(ys);
        const float w   = ys - y0f;
        wyh[ky] = __float2half2_rn(w);
        uyh[ky] = __float2half2_rn(1.0f - w);
        int y0 = min(max((int)y0f, 0), HH - 1);
        y0i[ky] = y0;
        y1i[ky] = min(y0 + 1, HH - 1);
    }

    const int c4 = threadIdx.x;
    const u64* __restrict__ base = g_fmh + b * (HH * WW * CPIX) + c4;
    const u64* __restrict__ R0 = base + y0i[0] * (WW * CPIX);
    const u64* __restrict__ R1 = base + y1i[0] * (WW * CPIX);
    const u64* __restrict__ R2 = base + y0i[1] * (WW * CPIX);
    const u64* __restrict__ R3 = base + y1i[1] * (WW * CPIX);

    float4* __restrict__ outp = (float4*)out + (blk * POOLED) * CPIX + c4;

    // Two cells per iteration: 32 LDG.64 issued back-to-back (one stall
    // window instead of two), then both cells' compute.
#pragma unroll 1
    for (int pw = 0; pw < POOLED - 1; pw += 2) {
        XW xa = xsetup(bx, sx, pw);
        XW xb = xsetup(bx, sx, pw + 1);
        u64 HA[16], HB[16];
        LOAD16(HA, xa);
        LOAD16(HB, xb);
        compute_cell(HA, xa, wyh[0], uyh[0], wyh[1], uyh[1], outp + pw * CPIX);
        compute_cell(HB, xb, wyh[0], uyh[0], wyh[1], uyh[1], outp + (pw + 1) * CPIX);
    }
    {   // peeled pw = 6
        XW xc = xsetup(bx, sx, POOLED - 1);
        u64 HC[16];
        LOAD16(HC, xc);
        compute_cell(HC, xc, wyh[0], uyh[0], wyh[1], uyh[1],
                     outp + (POOLED - 1) * CPIX);
    }
}

extern "C" void kernel_launch(void* const* d_in, const int* in_sizes, int n_in,
                              void* d_out, int out_size) {
    const float* fm   = (const float*)d_in[0];   // (2,50,50,512) f32
    const float* rois = (const float*)d_in[1];   // (2,128,4) f32
    float* out = (float*)d_out;                  // (256,7,7,512) f32

    conv_kernel<<<1250, 256>>>((const float4*)fm);       // 320,000 threads exact
    roi_pool_kernel<<<NROI * POOLED, 128>>>(rois, out);  // 1792 blocks
}